// round 14
// baseline (speedup 1.0000x reference)
#include <cuda_runtime.h>
#include <float.h>
#include <math.h>

#define MAXROWS 8192
#define D32     32000
#define NT1     512
#define NW1     (NT1 / 32)
#define KFULL   15             // 8000 f4 = 15*512 + 320
#define REM     320
#define NT2     128            // 4 row-warps per K2 block
#define WPB     4
#define ECAP    2560           // pooled element slots per row-warp (smem)

__device__ float    g_rowmax[MAXROWS];
__device__ unsigned g_mask[MAXROWS * NT1];
__device__ int      g_flag[MAXROWS];
__device__ float    g_rowloss[MAXROWS];

#define M4(v) fmaxf(fmaxf((v).x, (v).y), fmaxf((v).z, (v).w))

__device__ __forceinline__ float warpMax(float v) {
#pragma unroll
    for (int o = 16; o; o >>= 1) v = fmaxf(v, __shfl_xor_sync(0xffffffffu, v, o));
    return v;
}
__device__ __forceinline__ float warpSumB(float v) {   // uniform, deterministic
#pragma unroll
    for (int o = 16; o; o >>= 1) v += __shfl_xor_sync(0xffffffffu, v, o);
    return v;
}

// ============ K1 (d==32000): pure rowmax stream + exact-threshold bits ============
// Measured 79.5 us @ 85% DRAM. Bit set iff f4max > rowmax-2 <=> f4 contains an
// element with X > maxX-1 = tau_lo0, superset of every bisection probe's support.
__global__ __launch_bounds__(NT1, 2) void filter32k(const float* __restrict__ in) {
    int row = blockIdx.x, tid = threadIdx.x;
    int lane = tid & 31, warp = tid >> 5;
    const float4* p4 = (const float4*)(in + (size_t)row * D32);
    __shared__ float swm[NW1];

    float m4[KFULL + 1];
#pragma unroll
    for (int k = 0; k < KFULL; k++) {
        float4 v = p4[k * NT1 + tid];
        m4[k] = M4(v);
    }
    if (tid < REM) {
        float4 v = p4[KFULL * NT1 + tid];
        m4[KFULL] = M4(v);
    } else m4[KFULL] = -FLT_MAX;

    float rm = m4[0];
#pragma unroll
    for (int k = 1; k <= KFULL; k++) rm = fmaxf(rm, m4[k]);

    float wv = warpMax(rm);
    if (lane == 0) swm[warp] = wv;
    __syncthreads();
    float bmax = swm[0];
#pragma unroll
    for (int w = 1; w < NW1; w++) bmax = fmaxf(bmax, swm[w]);

    float th = bmax - 2.0f;
    unsigned hit = 0;
#pragma unroll
    for (int k = 0; k <= KFULL; k++)
        if (m4[k] > th) hit |= (1u << k);

    g_mask[row * NT1 + tid] = hit;
    if (tid == 0) g_rowmax[row] = bmax;
}

// ============ K2 (d==32000): warp-per-row, pooled SMEM elements ============
__global__ __launch_bounds__(NT2) void bisect32k(const float* __restrict__ in,
                                                 const void* __restrict__ tgt, int n) {
    int lane = threadIdx.x & 31;
    int w    = threadIdx.x >> 5;
    int row  = blockIdx.x * WPB + w;
    __shared__ float pool[WPB][ECAP];          // 40 KB
    if (row >= n) return;                      // warp-autonomous, no barriers

    const float* xr = in + (size_t)row * D32;
    const float4* p4 = (const float4*)xr;

    float bmax = g_rowmax[row];
    float thr  = bmax - 2.0f;                  // raw units; element-exact support

    // ---- masks (coalesced) ----
    unsigned hm[16];
#pragma unroll
    for (int j = 0; j < 16; j++) hm[j] = g_mask[row * NT1 + lane + 32 * j];

    // ---- pass A: load hit f4s (scattered), count elements > thr ----
    int ec = 0;
#pragma unroll 1
    for (int j = 0; j < 16; j++) {
        unsigned m = hm[j];
        int c = lane + 32 * j;
        while (m) {
            int b = __ffs(m) - 1;
            m &= m - 1;
            float4 v = p4[b * NT1 + c];
            ec += (v.x > thr) + (v.y > thr) + (v.z > thr) + (v.w > thr);
        }
    }
    // warp exclusive scan -> deterministic pooled positions
    int incl = ec;
#pragma unroll
    for (int o = 1; o < 32; o <<= 1) {
        int t = __shfl_up_sync(0xffffffffu, incl, o);
        if (lane >= o) incl += t;
    }
    int total = __shfl_sync(0xffffffffu, incl, 31);
    int base  = incl - ec;

    bool ovf = (total > ECAP);
    if (lane == 0) g_flag[row] = ovf ? 1 : 0;
    if (ovf) return;                           // K3 handles this row

    // ---- pass B: reload (L2-hot) and write elements X = 0.5*x to pool ----
    {
        int pos = base;
#pragma unroll 1
        for (int j = 0; j < 16; j++) {
            unsigned m = hm[j];
            int c = lane + 32 * j;
            while (m) {
                int b = __ffs(m) - 1;
                m &= m - 1;
                float4 v = p4[b * NT1 + c];
                if (v.x > thr) pool[w][pos++] = 0.5f * v.x;
                if (v.y > thr) pool[w][pos++] = 0.5f * v.y;
                if (v.z > thr) pool[w][pos++] = 0.5f * v.z;
                if (v.w > thr) pool[w][pos++] = 0.5f * v.w;
            }
        }
    }
    __syncwarp();

    float maxX    = 0.5f * bmax;
    float tau_lo0 = maxX - 1.0f;
    float tau_hi0 = maxX - 0.00559017f;        // maxX - (1/32000)^0.5

    // ---- f_lo over pool (exact: excluded elements contribute 0) ----
    float fl = 0.f;
    for (int i = lane; i < total; i += 32) {
        float t = pool[w][i] - tau_lo0;
        if (t > 0.f) fl = fmaf(t, t, fl);
    }
    float f_lo = warpSumB(fl) - 1.0f;

    // ---- 15 bisection iterations, all LDS-resident ----
    float tau_lo = tau_lo0;
    float dm     = tau_hi0 - tau_lo0;
    float tau_m  = tau_lo0;
#pragma unroll 1
    for (int it = 0; it < 15; it++) {
        dm *= 0.5f;
        tau_m = tau_lo + dm;
        float s = 0.f;
        for (int i = lane; i < total; i += 32) {
            float t = fmaxf(pool[w][i] - tau_m, 0.f);
            s = fmaf(t, t, s);
        }
        float fm = warpSumB(s) - 1.0f;
        tau_lo = (fm * f_lo >= 0.f) ? tau_m : tau_lo;   // uniform across warp
    }

    // ---- finals at last tau_m ----
    float s3 = 0.f, px = 0.f;
    for (int i = lane; i < total; i += 32) {
        float X = pool[w][i];
        float t = fmaxf(X - tau_m, 0.f);
        float p = t * t;
        s3 = fmaf(p, t, s3);
        px = fmaf(p, X, px);
    }
    float S3 = warpSumB(s3);
    float PX = warpSumB(px);

    // ---- target (lane-parallel dtype sniff) + loss ----
    {
        const int* t32 = (const int*)tgt;
        int lim = (n < 32) ? n : 32;
        int z = 1;
        if (lane < lim) z = (t32[2 * lane + 1] == 0);
        bool is64 = __all_sync(0xffffffffu, z != 0);
        if (lane == 0) {
            long long v = is64 ? ((const long long*)tgt)[row] : (long long)t32[row];
            int t = (int)v;
            if (t < 0 || t >= D32) t = 0;
            float xt = __ldg(xr + t);
            // loss = (1-S3)/(alpha*(alpha-1)) + sum(p*input) - input[target]
            //      = (1-S3)/0.75 + 2*PX - xt          (input = 2*X)
            g_rowloss[row] = (1.0f - S3) / 0.75f + 2.0f * PX - xt;
        }
    }
}

// ============ shared block-parallel reference core ============
__device__ __forceinline__ float blockSumAllG(float v, float* sbuf) {
    int lane = threadIdx.x & 31, warp = threadIdx.x >> 5;
#pragma unroll
    for (int o = 16; o; o >>= 1) v += __shfl_xor_sync(0xffffffffu, v, o);
    __syncthreads();
    if (lane == 0) sbuf[warp] = v;
    __syncthreads();
    float s = 0.f;
#pragma unroll
    for (int w = 0; w < 8; w++) s += sbuf[w];
    return s;
}

__device__ void ref_row(const float* xr, const void* tgt, int d, int n, int row,
                        float* sred) {
    float m = -FLT_MAX;
    for (int i = threadIdx.x; i < d; i += 256) m = fmaxf(m, xr[i]);
    m = warpMax(m);
    __syncthreads();
    if ((threadIdx.x & 31) == 0) sred[threadIdx.x >> 5] = m;
    __syncthreads();
    float bmax = sred[0];
#pragma unroll
    for (int w = 1; w < 8; w++) bmax = fmaxf(bmax, sred[w]);
    float maxX = 0.5f * bmax;
    float tl = maxX - 1.0f;
    float th0 = maxX - (float)(1.0 / sqrt((double)d));
    float s = 0.f;
    for (int i = threadIdx.x; i < d; i += 256) {
        float q = fmaxf(fmaf(0.5f, __ldg(xr + i), -tl), 0.f);
        s = fmaf(q, q, s);
    }
    float f_lo = blockSumAllG(s, sred) - 1.0f;
    float dm = th0 - tl, tm = tl;
#pragma unroll 1
    for (int it = 0; it < 15; it++) {
        dm *= 0.5f;
        tm = tl + dm;
        float q2 = 0.f;
        for (int i = threadIdx.x; i < d; i += 256) {
            float q = fmaxf(fmaf(0.5f, __ldg(xr + i), -tm), 0.f);
            q2 = fmaf(q, q, q2);
        }
        float fm = blockSumAllG(q2, sred) - 1.0f;
        tl = (fm * f_lo >= 0.f) ? tm : tl;
    }
    float s3 = 0.f, px = 0.f;
    for (int i = threadIdx.x; i < d; i += 256) {
        float X = 0.5f * __ldg(xr + i);
        float q = fmaxf(X - tm, 0.f);
        float p = q * q;
        s3 = fmaf(p, q, s3);
        px = fmaf(p, X, px);
    }
    float S3 = blockSumAllG(s3, sred);
    float PX = blockSumAllG(px, sred);
    if (threadIdx.x == 0) {
        const int* t32 = (const int*)tgt;
        int lim = (n < 32) ? n : 32;
        bool is64 = true;
        for (int i = 0; i < lim; i++) is64 = is64 && (t32[2 * i + 1] == 0);
        long long v = is64 ? ((const long long*)tgt)[row] : (long long)t32[row];
        int t = (int)v;
        if (t < 0 || t >= d) t = 0;
        g_rowloss[row] = (1.0f - S3) / 0.75f + 2.0f * PX - __ldg(xr + t);
    }
}

// K3: flagged (overflow) rows only; everyone else exits immediately.
__global__ __launch_bounds__(256) void flagged32k(const float* __restrict__ in,
                                                  const void* __restrict__ tgt, int n) {
    int row = blockIdx.x;
    if (!g_flag[row]) return;
    __shared__ float sred[8];
    ref_row(in + (size_t)row * D32, tgt, D32, n, row, sred);
}

// generic fallback (any d)
__global__ __launch_bounds__(256) void tsallis_gen(const float* __restrict__ in,
                                                   const void* __restrict__ tgt,
                                                   int d, int n) {
    int row = blockIdx.x;
    __shared__ float sred[8];
    ref_row(in + (size_t)row * d, tgt, d, n, row, sred);
}

// mean over rows
__global__ __launch_bounds__(1024) void reduce_kernel(float* __restrict__ out, int n) {
    __shared__ float sbuf[32];
    float s = 0.f;
    for (int i = threadIdx.x; i < n; i += 1024) s += g_rowloss[i];
#pragma unroll
    for (int o = 16; o; o >>= 1) s += __shfl_down_sync(0xffffffffu, s, o);
    if ((threadIdx.x & 31) == 0) sbuf[threadIdx.x >> 5] = s;
    __syncthreads();
    if (threadIdx.x < 32) {
        float x = sbuf[threadIdx.x];
#pragma unroll
        for (int o = 16; o; o >>= 1) x += __shfl_down_sync(0xffffffffu, x, o);
        if (threadIdx.x == 0) out[0] = x / (float)n;
    }
}

extern "C" void kernel_launch(void* const* d_in, const int* in_sizes, int n_in,
                              void* d_out, int out_size) {
    int idx_in = 0, idx_tg = 1;
    if (n_in >= 2 && in_sizes[1] > in_sizes[0]) { idx_in = 1; idx_tg = 0; }
    const float* in  = (const float*)d_in[idx_in];
    const void*  tgt = d_in[idx_tg];

    int n = in_sizes[idx_tg];
    if (n <= 0) n = 1;
    int d = in_sizes[idx_in] / n;
    if (n > MAXROWS) n = MAXROWS;

    if (d == D32) {
        filter32k<<<n, NT1>>>(in);
        bisect32k<<<(n + WPB - 1) / WPB, NT2>>>(in, tgt, n);
        flagged32k<<<n, 256>>>(in, tgt, n);
    } else {
        tsallis_gen<<<n, 256>>>(in, tgt, d, n);
    }
    reduce_kernel<<<1, 1024>>>((float*)d_out, n);
}

// round 15
// speedup vs baseline: 1.0517x; 1.0517x over previous
#include <cuda_runtime.h>
#include <float.h>
#include <math.h>

#define MAXROWS 8192
#define D32     32000
#define NTF     512
#define NWF     (NTF / 32)
#define SLOTS   12                 // per-thread f4 slots (dynamic smem, 96 KB)

__device__ float g_rowloss[MAXROWS];

#define M4(v) fmaxf(fmaxf((v).x, (v).y), fmaxf((v).z, (v).w))

__device__ __forceinline__ float warpMax(float v) {
#pragma unroll
    for (int o = 16; o; o >>= 1) v = fmaxf(v, __shfl_xor_sync(0xffffffffu, v, o));
    return v;
}
// Block sum returned to ALL threads (fixed order -> deterministic, uniform).
__device__ __forceinline__ float blockSumAll(float v, float* sbuf, int nw) {
    int lane = threadIdx.x & 31, warp = threadIdx.x >> 5;
#pragma unroll
    for (int o = 16; o; o >>= 1) v += __shfl_xor_sync(0xffffffffu, v, o);
    __syncthreads();
    if (lane == 0) sbuf[warp] = v;
    __syncthreads();
    float s = 0.f;
    for (int w = 0; w < nw; w++) s += sbuf[w];
    return s;
}

// ============ fused kernel, d == 32000 ============
// Stream shape = proven 79.5us filter (batched unconditional LDG.128 + FMAX trees),
// plus predicated STS.128 of hit f4s into per-thread smem slots (data in registers,
// NO tail re-fetch). Threshold = (stale block max) - 2 <= rowmax-2 -> superset of
// every element with X > maxX-1 = tau_lo0 > any bisection probe's cutoff.
__global__ __launch_bounds__(NTF, 2) void tsallis32k(const float* __restrict__ in,
                                                     const void* __restrict__ tgt, int n) {
    extern __shared__ float4 cand[];          // [SLOTS][NTF] slot-major
    __shared__ float swm[NWF];
    __shared__ float sred[NWF];
    __shared__ int   s_slow;

    int row = blockIdx.x, tid = threadIdx.x;
    int lane = tid & 31, warp = tid >> 5;
    const float*  xr = in + (size_t)row * D32;
    const float4* p4 = (const float4*)xr;
    if (tid == 0) s_slow = 0;

    // ---- warm-up: rounds 0..4, only per-f4 maxes in registers ----
    float m4a[5];
#pragma unroll
    for (int u = 0; u < 5; u++) m4a[u] = M4(p4[u * NTF + tid]);
    float rm = fmaxf(fmaxf(fmaxf(m4a[0], m4a[1]), fmaxf(m4a[2], m4a[3])), m4a[4]);
    {
        float wv = warpMax(rm);
        if (lane == 0) swm[warp] = wv;
        __syncthreads();
    }
    float bm = swm[0];
#pragma unroll
    for (int w = 1; w < NWF; w++) bm = fmaxf(bm, swm[w]);
    float th = bm - 2.0f;                     // raw units
    __syncthreads();                          // swm reused later

    int c = 0;
    // warm-up hits: reload from L1/L2 (tiny count), store whole f4
#pragma unroll
    for (int u = 0; u < 5; u++) {
        if (m4a[u] > th) {
            float4 v = p4[u * NTF + tid];
            if (c < SLOTS) cand[c * NTF + tid] = v;
            c++;
        }
    }

    // ---- group 1: rounds 5..9 (unconditional batched loads) ----
    {
        float4 v[5]; float m4[5];
#pragma unroll
        for (int u = 0; u < 5; u++) v[u] = p4[(5 + u) * NTF + tid];
#pragma unroll
        for (int u = 0; u < 5; u++) m4[u] = M4(v[u]);
#pragma unroll
        for (int u = 0; u < 5; u++) {
            if (m4[u] > th) {
                if (c < SLOTS) cand[c * NTF + tid] = v[u];
                c++;
            }
        }
        float gm = fmaxf(fmaxf(fmaxf(m4[0], m4[1]), fmaxf(m4[2], m4[3])), m4[4]);
        rm = fmaxf(rm, gm);
    }
    // refresh threshold (tightens; still <= rowmax-2 -> superset-safe)
    {
        float wv = warpMax(rm);
        __syncthreads();
        if (lane == 0) swm[warp] = wv;
        __syncthreads();
        float b2 = swm[0];
#pragma unroll
        for (int w = 1; w < NWF; w++) b2 = fmaxf(b2, swm[w]);
        th = fmaxf(th, b2 - 2.0f);
        __syncthreads();
    }
    // ---- group 2: rounds 10..14 ----
    {
        float4 v[5]; float m4[5];
#pragma unroll
        for (int u = 0; u < 5; u++) v[u] = p4[(10 + u) * NTF + tid];
#pragma unroll
        for (int u = 0; u < 5; u++) m4[u] = M4(v[u]);
#pragma unroll
        for (int u = 0; u < 5; u++) {
            if (m4[u] > th) {
                if (c < SLOTS) cand[c * NTF + tid] = v[u];
                c++;
            }
        }
        float gm = fmaxf(fmaxf(fmaxf(m4[0], m4[1]), fmaxf(m4[2], m4[3])), m4[4]);
        rm = fmaxf(rm, gm);
    }
    // ---- remainder: f4 indices 7680..7999 (tid < 320) ----
    if (tid < 320) {
        float4 v = p4[15 * NTF + tid];
        float m = M4(v);
        rm = fmaxf(rm, m);
        if (m > th) {
            if (c < SLOTS) cand[c * NTF + tid] = v;
            c++;
        }
    }
    if (c > SLOTS) atomicOr(&s_slow, 1);

    // ---- exact block max ----
    {
        float wv = warpMax(rm);
        __syncthreads();
        if (lane == 0) swm[warp] = wv;
        __syncthreads();                      // also publishes s_slow + cand
    }
    float bmax = swm[0];
#pragma unroll
    for (int w = 1; w < NWF; w++) bmax = fmaxf(bmax, swm[w]);

    float maxX    = 0.5f * bmax;
    float tau_lo0 = maxX - 1.0f;
    float tau_hi0 = maxX - 0.005590169943749474f;   // maxX - (1/32000)^0.5
    bool  slow    = (s_slow != 0);                  // block-uniform
    int   myc     = slow ? 0 : c;

    float S3, PX, tau_m;
    if (!slow) {
        // ---- f_lo over cand (exact: every element > rowmax-2 is present;
        //      extras contribute 0 to relu sums at tau >= tau_lo0) ----
        float fl = 0.f;
        for (int j = 0; j < myc; j++) {
            float4 v = cand[j * NTF + tid];
            float q;
            q = fmaxf(fmaf(0.5f, v.x, -tau_lo0), 0.f); fl = fmaf(q, q, fl);
            q = fmaxf(fmaf(0.5f, v.y, -tau_lo0), 0.f); fl = fmaf(q, q, fl);
            q = fmaxf(fmaf(0.5f, v.z, -tau_lo0), 0.f); fl = fmaf(q, q, fl);
            q = fmaxf(fmaf(0.5f, v.w, -tau_lo0), 0.f); fl = fmaf(q, q, fl);
        }
        float f_lo = blockSumAll(fl, sred, NWF) - 1.0f;

        // ---- 15 bisection iterations, all smem-resident ----
        float tau_lo = tau_lo0;
        float dm     = tau_hi0 - tau_lo0;
        tau_m = tau_lo0;
#pragma unroll 1
        for (int it = 0; it < 15; it++) {
            dm *= 0.5f;
            tau_m = tau_lo + dm;
            float s = 0.f;
            for (int j = 0; j < myc; j++) {
                float4 v = cand[j * NTF + tid];
                float q;
                q = fmaxf(fmaf(0.5f, v.x, -tau_m), 0.f); s = fmaf(q, q, s);
                q = fmaxf(fmaf(0.5f, v.y, -tau_m), 0.f); s = fmaf(q, q, s);
                q = fmaxf(fmaf(0.5f, v.z, -tau_m), 0.f); s = fmaf(q, q, s);
                q = fmaxf(fmaf(0.5f, v.w, -tau_m), 0.f); s = fmaf(q, q, s);
            }
            float fm = blockSumAll(s, sred, NWF) - 1.0f;
            tau_lo = (fm * f_lo >= 0.f) ? tau_m : tau_lo;   // uniform
        }

        // ---- finals at last tau_m ----
        float s3 = 0.f, px = 0.f;
        for (int j = 0; j < myc; j++) {
            float4 v = cand[j * NTF + tid];
            float X, q, p;
            X = 0.5f * v.x; q = fmaxf(X - tau_m, 0.f); p = q * q; s3 = fmaf(p, q, s3); px = fmaf(p, X, px);
            X = 0.5f * v.y; q = fmaxf(X - tau_m, 0.f); p = q * q; s3 = fmaf(p, q, s3); px = fmaf(p, X, px);
            X = 0.5f * v.z; q = fmaxf(X - tau_m, 0.f); p = q * q; s3 = fmaf(p, q, s3); px = fmaf(p, X, px);
            X = 0.5f * v.w; q = fmaxf(X - tau_m, 0.f); p = q * q; s3 = fmaf(p, q, s3); px = fmaf(p, X, px);
        }
        S3 = blockSumAll(s3, sred, NWF);
        PX = blockSumAll(px, sred, NWF);
    } else {
        // ---- block-parallel full-reference slow path (overflow rows, ~1) ----
        float tl = tau_lo0;
        float s0 = 0.f;
        for (int i = tid; i < D32; i += NTF) {
            float q = fmaxf(fmaf(0.5f, __ldg(xr + i), -tl), 0.f);
            s0 = fmaf(q, q, s0);
        }
        float f_lo = blockSumAll(s0, sred, NWF) - 1.0f;
        float dm = tau_hi0 - tl, tm = tl;
#pragma unroll 1
        for (int it = 0; it < 15; it++) {
            dm *= 0.5f;
            tm = tl + dm;
            float q2 = 0.f;
            for (int i = tid; i < D32; i += NTF) {
                float q = fmaxf(fmaf(0.5f, __ldg(xr + i), -tm), 0.f);
                q2 = fmaf(q, q, q2);
            }
            float fm = blockSumAll(q2, sred, NWF) - 1.0f;
            tl = (fm * f_lo >= 0.f) ? tm : tl;
        }
        tau_m = tm;
        float s3 = 0.f, px = 0.f;
        for (int i = tid; i < D32; i += NTF) {
            float X = 0.5f * __ldg(xr + i);
            float q = fmaxf(X - tau_m, 0.f);
            float p = q * q;
            s3 = fmaf(p, q, s3);
            px = fmaf(p, X, px);
        }
        S3 = blockSumAll(s3, sred, NWF);
        PX = blockSumAll(px, sred, NWF);
    }

    if (tid == 0) {
        const int* t32 = (const int*)tgt;
        int lim = (n < 32) ? n : 32;
        bool is64 = true;
        for (int i = 0; i < lim; i++) is64 = is64 && (t32[2 * i + 1] == 0);
        long long v = is64 ? ((const long long*)tgt)[row] : (long long)t32[row];
        int t = (int)v;
        if (t < 0 || t >= D32) t = 0;
        float xt = __ldg(xr + t);
        // loss = (1-S3)/(alpha*(alpha-1)) + sum(p*input) - input[target]
        //      = (1-S3)/0.75 + 2*PX - xt          (input = 2*X)
        g_rowloss[row] = (1.0f - S3) / 0.75f + 2.0f * PX - xt;
    }
}

// ============ generic fallback (any d) ============
__global__ __launch_bounds__(256) void tsallis_gen(const float* __restrict__ in,
                                                   const void* __restrict__ tgt,
                                                   int d, int n) {
    int row = blockIdx.x;
    const float* xr = in + (size_t)row * d;
    __shared__ float sred[8];
    float m = -FLT_MAX;
    for (int i = threadIdx.x; i < d; i += 256) m = fmaxf(m, xr[i]);
    m = warpMax(m);
    __syncthreads();
    if ((threadIdx.x & 31) == 0) sred[threadIdx.x >> 5] = m;
    __syncthreads();
    float bmax = sred[0];
#pragma unroll
    for (int w = 1; w < 8; w++) bmax = fmaxf(bmax, sred[w]);
    float maxX = 0.5f * bmax;
    float tl = maxX - 1.0f;
    float th0 = maxX - (float)(1.0 / sqrt((double)d));
    float s = 0.f;
    for (int i = threadIdx.x; i < d; i += 256) {
        float q = fmaxf(fmaf(0.5f, __ldg(xr + i), -tl), 0.f);
        s = fmaf(q, q, s);
    }
    float f_lo = blockSumAll(s, sred, 8) - 1.0f;
    float dm = th0 - tl, tm = tl;
#pragma unroll 1
    for (int it = 0; it < 15; it++) {
        dm *= 0.5f;
        tm = tl + dm;
        float q2 = 0.f;
        for (int i = threadIdx.x; i < d; i += 256) {
            float q = fmaxf(fmaf(0.5f, __ldg(xr + i), -tm), 0.f);
            q2 = fmaf(q, q, q2);
        }
        float fm = blockSumAll(q2, sred, 8) - 1.0f;
        tl = (fm * f_lo >= 0.f) ? tm : tl;
    }
    float s3 = 0.f, px = 0.f;
    for (int i = threadIdx.x; i < d; i += 256) {
        float X = 0.5f * __ldg(xr + i);
        float q = fmaxf(X - tm, 0.f);
        float p = q * q;
        s3 = fmaf(p, q, s3);
        px = fmaf(p, X, px);
    }
    float S3 = blockSumAll(s3, sred, 8);
    float PX = blockSumAll(px, sred, 8);
    if (threadIdx.x == 0) {
        const int* t32 = (const int*)tgt;
        int lim = (n < 32) ? n : 32;
        bool is64 = true;
        for (int i = 0; i < lim; i++) is64 = is64 && (t32[2 * i + 1] == 0);
        long long v = is64 ? ((const long long*)tgt)[row] : (long long)t32[row];
        int t = (int)v;
        if (t < 0 || t >= d) t = 0;
        g_rowloss[row] = (1.0f - S3) / 0.75f + 2.0f * PX - __ldg(xr + t);
    }
}

// ============ mean over rows ============
__global__ __launch_bounds__(1024) void reduce_kernel(float* __restrict__ out, int n) {
    __shared__ float sbuf[32];
    float s = 0.f;
    for (int i = threadIdx.x; i < n; i += 1024) s += g_rowloss[i];
#pragma unroll
    for (int o = 16; o; o >>= 1) s += __shfl_down_sync(0xffffffffu, s, o);
    if ((threadIdx.x & 31) == 0) sbuf[threadIdx.x >> 5] = s;
    __syncthreads();
    if (threadIdx.x < 32) {
        float x = sbuf[threadIdx.x];
#pragma unroll
        for (int o = 16; o; o >>= 1) x += __shfl_down_sync(0xffffffffu, x, o);
        if (threadIdx.x == 0) out[0] = x / (float)n;
    }
}

extern "C" void kernel_launch(void* const* d_in, const int* in_sizes, int n_in,
                              void* d_out, int out_size) {
    int idx_in = 0, idx_tg = 1;
    if (n_in >= 2 && in_sizes[1] > in_sizes[0]) { idx_in = 1; idx_tg = 0; }
    const float* in  = (const float*)d_in[idx_in];
    const void*  tgt = d_in[idx_tg];

    int n = in_sizes[idx_tg];
    if (n <= 0) n = 1;
    int d = in_sizes[idx_in] / n;
    if (n > MAXROWS) n = MAXROWS;

    if (d == D32) {
        int dyn = SLOTS * NTF * (int)sizeof(float4);      // 96 KB
        cudaFuncSetAttribute(tsallis32k, cudaFuncAttributeMaxDynamicSharedMemorySize, dyn);
        tsallis32k<<<n, NTF, dyn>>>(in, tgt, n);
    } else {
        tsallis_gen<<<n, 256>>>(in, tgt, d, n);
    }
    reduce_kernel<<<1, 1024>>>((float*)d_out, n);
}